// round 6
// baseline (speedup 1.0000x reference)
#include <cuda_runtime.h>

#define BIN 256
#define IM 256
#define NPIX (IM * IM)          // 65536
#define NBLOCKS 512
#define NTHREADS 256            // 131072 threads total, all co-resident

// Scratch: 4 histograms ({inp,ref} x {b0,b1}) of 256x256 float = 1 MB.
// Zero-initialized at module load; re-zeroed in phase B after reading, so
// every kernel_launch call (and every graph replay) starts from zeros.
__device__ float g_hist[4 * BIN * BIN];

// Monotonic barrier counter. Never reset: each kernel run consumes exactly
// NBLOCKS increments, so epoch = my/NBLOCKS is uniform within a run and the
// barrier is correct across unlimited graph replays.
__device__ unsigned long long g_bar;

// Triangular-kernel weight, numerics matching the reference exactly:
//   bias_k = 1 - 2k/256 (exact dyadic), a1 = u + bias_k, w = relu(1 - |a1|*255)
__device__ __forceinline__ float tri_w(float u, int k) {
    float a1 = u + (1.0f - (float)k * 0.0078125f);
    return fmaxf(0.0f, 1.0f - fabsf(a1) * 255.0f);
}

// Scatter one (image t, batch b, pixel p): at most 2 bins active per axis,
// usually exactly 1 (support 1/255 vs half-pitch 1/256) -> ~1.3 atomics avg.
__device__ __forceinline__ void scatter_item(int t, int idx,
                                             const float* __restrict__ img) {
    int b = idx >> 16;            // batch
    int p = idx & (NPIX - 1);     // pixel

    float xa = img[(b * 2 + 0) * NPIX + p];   // ch0 -> r axis (contig)
    float xb = img[(b * 2 + 1) * NPIX + p];   // ch1 -> j axis (row)
    float ua = (xa + 1.0f) * 0.5f;
    float ub = (xb + 1.0f) * 0.5f;

    int ka = (int)floorf(ua * 128.0f + 128.0f);
    int kb = (int)floorf(ub * 128.0f + 128.0f);

    float wa0 = tri_w(ua, ka);
    float wa1 = tri_w(ua, ka + 1);
    float wb0 = tri_w(ub, kb);
    float wb1 = tri_w(ub, kb + 1);

    bool a0 = wa0 > 0.0f;
    bool a1 = wa1 > 0.0f && (ka + 1) < BIN;
    bool b0 = wb0 > 0.0f;
    bool b1 = wb1 > 0.0f && (kb + 1) < BIN;

    float* H = g_hist + (t * 2 + b) * BIN * BIN;
    float* row0 = H + kb * BIN;
    if (b0) {
        if (a0) atomicAdd(row0 + ka,     wb0 * wa0);
        if (a1) atomicAdd(row0 + ka + 1, wb0 * wa1);
    }
    if (b1) {
        float* row1 = row0 + BIN;
        if (a0) atomicAdd(row1 + ka,     wb1 * wa0);
        if (a1) atomicAdd(row1 + ka + 1, wb1 * wa1);
    }
}

__global__ void __launch_bounds__(NTHREADS)
fused_kernel(const float* __restrict__ inp,
             const float* __restrict__ ref,
             float* __restrict__ out) {
    int idx = blockIdx.x * NTHREADS + threadIdx.x;   // 0 .. 131071

    // ---------------- Phase A: scatter (2 items per thread) ----------------
    scatter_item(0, idx, inp);
    scatter_item(1, idx, ref);

    // ---------------- Inter-block barrier (epoch counter) ----------------
    __threadfence();     // order my atomics before arrival
    __syncthreads();     // whole block done before block arrives
    if (threadIdx.x == 0) {
        unsigned long long my = atomicAdd(&g_bar, 1ULL);
        unsigned long long target =
            (my / (unsigned long long)gridDim.x + 1ULL) *
            (unsigned long long)gridDim.x;
        unsigned long long v;
        do {
            asm volatile("ld.acquire.gpu.u64 %0, [%1];"
                         : "=l"(v)
                         : "l"(&g_bar)
                         : "memory");
        } while (v < target);
    }
    __syncthreads();
    __threadfence();     // make all blocks' atomics visible to my loads

    // ---------------- Phase B: Huber loss + re-zero ----------------
    // out[b,0,j,r]: 2*65536 elements == one per thread, coalesced.
    {
        int b  = idx >> 16;
        int jr = idx & (BIN * BIN - 1);

        int oi = (0 * 2 + b) * BIN * BIN + jr;   // inp hist cell
        int gi = (1 * 2 + b) * BIN * BIN + jr;   // ref hist cell
        float hi = g_hist[oi];
        float hg = g_hist[gi];
        g_hist[oi] = 0.0f;
        g_hist[gi] = 0.0f;

        const float inv = 1.0f / (float)NPIX;
        float m = fabsf(hi - hg) * inv;
        out[idx] = (m < 0.01f) ? 50.0f * m * m : m - 0.005f;
    }
}

// ---------------------------------------------------------------------------
extern "C" void kernel_launch(void* const* d_in, const int* in_sizes, int n_in,
                              void* d_out, int out_size) {
    const float* inp = (const float*)d_in[0];
    const float* ref = (const float*)d_in[1];
    float* out = (float*)d_out;

    fused_kernel<<<NBLOCKS, NTHREADS>>>(inp, ref, out);
}

// round 7
// speedup vs baseline: 1.0058x; 1.0058x over previous
#include <cuda_runtime.h>

#define BIN 256
#define IM 256
#define NPIX (IM * IM)          // 65536
#define NBLOCKS 512
#define NTHREADS 256            // 131072 threads, all co-resident (4 blk/SM)

// Scratch: 4 histograms ({inp,ref} x {b0,b1}) of 256x256 float = 1 MB.
// Zero-initialized at module load; re-zeroed in phase B after reading, so
// every kernel_launch call (and every graph replay) starts from zeros.
__device__ float g_hist[4 * BIN * BIN];

// Monotonic barrier counter (never reset -> graph-replay safe: each run
// consumes exactly NBLOCKS increments; epoch = my/NBLOCKS uniform per run).
__device__ unsigned long long g_bar;

// Triangular-kernel weight, numerics matching the reference exactly:
//   bias_k = 1 - 2k/256 (exact dyadic), a1 = u + bias_k, w = relu(1 - |a1|*255)
__device__ __forceinline__ float tri_w(float u, int k) {
    float a1 = u + (1.0f - (float)k * 0.0078125f);
    return fmaxf(0.0f, 1.0f - fabsf(a1) * 255.0f);
}

// Scatter one pixel (channel values xa, xb) into histogram H.
// At most 2 bins active per axis, usually exactly 1 (support 1/255 vs
// half-pitch 1/256) -> ~1.3 atomics per pixel thanks to the predicates.
__device__ __forceinline__ void scatter_pixel(float xa, float xb,
                                              float* __restrict__ H) {
    float ua = (xa + 1.0f) * 0.5f;
    float ub = (xb + 1.0f) * 0.5f;

    // t = 128u+128 in [128,256] (positive) -> int truncation == floor
    int ka = (int)(ua * 128.0f + 128.0f);
    int kb = (int)(ub * 128.0f + 128.0f);

    float wa0 = tri_w(ua, ka);
    float wa1 = tri_w(ua, ka + 1);
    float wb0 = tri_w(ub, kb);
    float wb1 = tri_w(ub, kb + 1);

    bool a0 = wa0 > 0.0f;
    bool a1 = wa1 > 0.0f && (ka + 1) < BIN;
    bool b0 = wb0 > 0.0f;
    bool b1 = wb1 > 0.0f && (kb + 1) < BIN;

    float* row0 = H + kb * BIN;
    if (b0) {
        if (a0) atomicAdd(row0 + ka,     wb0 * wa0);
        if (a1) atomicAdd(row0 + ka + 1, wb0 * wa1);
    }
    if (b1) {
        float* row1 = row0 + BIN;
        if (a0) atomicAdd(row1 + ka,     wb1 * wa0);
        if (a1) atomicAdd(row1 + ka + 1, wb1 * wa1);
    }
}

__global__ void __launch_bounds__(NTHREADS)
fused_kernel(const float* __restrict__ inp,
             const float* __restrict__ ref,
             float* __restrict__ out) {
    int idx = blockIdx.x * NTHREADS + threadIdx.x;   // 0 .. 131071

    // ---------------- Phase A: scatter (one 2-pixel group / thread) --------
    // idx -> (t, b, q): t = image, b = batch, q = float2 group (2 pixels)
    {
        int t = idx >> 16;                 // 0=inp, 1=ref
        int b = (idx >> 15) & 1;           // batch
        int q = idx & (NPIX / 2 - 1);      // float2 index within plane

        const float* img = (t == 0) ? inp : ref;
        const float2* cha = reinterpret_cast<const float2*>(
            img + (b * 2 + 0) * NPIX);     // ch0 -> r axis
        const float2* chb = reinterpret_cast<const float2*>(
            img + (b * 2 + 1) * NPIX);     // ch1 -> j axis

        float2 va = cha[q];
        float2 vb = chb[q];

        float* H = g_hist + (t * 2 + b) * BIN * BIN;
        scatter_pixel(va.x, vb.x, H);
        scatter_pixel(va.y, vb.y, H);
    }

    // ---------------- Inter-block barrier (epoch counter) ----------------
    __threadfence();     // my REDs globally visible before arrival
    __syncthreads();     // whole block done before block arrives
    if (threadIdx.x == 0) {
        unsigned long long my = atomicAdd(&g_bar, 1ULL);
        unsigned long long target =
            (my / (unsigned long long)NBLOCKS + 1ULL) *
            (unsigned long long)NBLOCKS;
        unsigned long long v;
        do {
            asm volatile("ld.relaxed.gpu.u64 %0, [%1];"
                         : "=l"(v) : "l"(&g_bar) : "memory");
        } while (v < target);
        asm volatile("fence.acq_rel.gpu;" ::: "memory");
    }
    __syncthreads();

    // ---------------- Phase B: Huber loss + re-zero ----------------
    // out[b,0,j,r]: 2*65536 elements == one per thread, coalesced.
    {
        int b  = idx >> 16;
        int jr = idx & (BIN * BIN - 1);

        int oi = (0 * 2 + b) * BIN * BIN + jr;   // inp hist cell
        int gi = (1 * 2 + b) * BIN * BIN + jr;   // ref hist cell
        float hi = g_hist[oi];
        float hg = g_hist[gi];
        g_hist[oi] = 0.0f;
        g_hist[gi] = 0.0f;

        const float inv = 1.0f / (float)NPIX;
        float m = fabsf(hi - hg) * inv;
        out[idx] = (m < 0.01f) ? 50.0f * m * m : m - 0.005f;
    }
}

// ---------------------------------------------------------------------------
extern "C" void kernel_launch(void* const* d_in, const int* in_sizes, int n_in,
                              void* d_out, int out_size) {
    const float* inp = (const float*)d_in[0];
    const float* ref = (const float*)d_in[1];
    float* out = (float*)d_out;

    fused_kernel<<<NBLOCKS, NTHREADS>>>(inp, ref, out);
}